// round 15
// baseline (speedup 1.0000x reference)
#include <cuda_runtime.h>

// ResidualDenseBlock: out = scan_{l=0..63}( tanh(out @ W[l]^T + b[l]) * m[l] + out ) * sum(gates)
//
// R15: XU=48-per-4-rows configuration (4x f32 tanh + 2x full-rate f16x2 tanh,
// mag-unpack on ALU instead of XU F2F) -- previously stall-bound (R7) with only
// 2 dependency chains/thread. Fix: 8 rows/thread = 4 independent chains to cover
// the pack->tanh->unpack latency. Packed f32x2 FMA throughout.

#define LAYERS 64
#define TPB    256

typedef unsigned long long u64;

__device__ __forceinline__ float tanh_f32(float x) {
    float y;
    asm("tanh.approx.f32 %0, %1;" : "=f"(y) : "f"(x));
    return y;
}
__device__ __forceinline__ unsigned tanh_h2(unsigned h) {
    unsigned r;
    asm("tanh.approx.f16x2 %0, %1;" : "=r"(r) : "r"(h));
    return r;
}
// d = { hi = cvt(%1), lo = cvt(%2) }   (F2FP: fixed-pipe, lat 4)
__device__ __forceinline__ unsigned pack_h2(float hi, float lo) {
    unsigned r;
    asm("cvt.rn.f16x2.f32 %0, %1, %2;" : "=r"(r) : "f"(hi), "f"(lo));
    return r;
}
// Exact f16 -> f32*2^-112 reinterpretation (ALU only; compensated by m112).
__device__ __forceinline__ float mag_lo(unsigned r) {
    unsigned b = ((r << 16) & 0x80000000u) | ((r << 13) & 0x0FFFE000u);
    return __uint_as_float(b);
}
__device__ __forceinline__ float mag_hi(unsigned r) {
    unsigned b = (r & 0x80000000u) | ((r >> 3) & 0x0FFFE000u);
    return __uint_as_float(b);
}
__device__ __forceinline__ u64 fma2(u64 a, u64 b, u64 c) {
    u64 d;
    asm("fma.rn.f32x2 %0, %1, %2, %3;" : "=l"(d) : "l"(a), "l"(b), "l"(c));
    return d;
}
__device__ __forceinline__ u64 mul2(u64 a, u64 b) {
    u64 d;
    asm("mul.rn.f32x2 %0, %1, %2;" : "=l"(d) : "l"(a), "l"(b));
    return d;
}
__device__ __forceinline__ u64 pk2(float lo, float hi) {
    u64 d;
    asm("mov.b64 %0, {%1, %2};" : "=l"(d) : "f"(lo), "f"(hi));
    return d;
}
__device__ __forceinline__ void up2(float& lo, float& hi, u64 s) {
    asm("mov.b64 {%0, %1}, %2;" : "=f"(lo), "=f"(hi) : "l"(s));
}

struct __align__(16) LayerP {
    u64 w00, w01, w10, w11, b0, b1, m, m112;  // broadcast (v,v) pairs; m112 = m*2^112
};

__global__ __launch_bounds__(TPB)
void rdb_kernel(const float4* __restrict__ x,
                const float*  __restrict__ W,
                const float*  __restrict__ b,
                const float*  __restrict__ masks,
                const float*  __restrict__ gates,
                float4* __restrict__ out,
                long long n4)                 // float4 count = BATCH/2
{
    __shared__ LayerP sP[LAYERS];
    __shared__ float  sG;

    const int tid = threadIdx.x;
    if (tid < LAYERS) {
        float w00 = W[tid*4+0], w01 = W[tid*4+1];
        float w10 = W[tid*4+2], w11 = W[tid*4+3];
        float b0 = b[tid*2+0], b1 = b[tid*2+1];
        float m = masks[tid];
        LayerP p;
        p.w00 = pk2(w00, w00); p.w01 = pk2(w01, w01);
        p.w10 = pk2(w10, w10); p.w11 = pk2(w11, w11);
        p.b0  = pk2(b0, b0);   p.b1  = pk2(b1, b1);
        p.m   = pk2(m, m);     p.m112 = pk2(m*0x1p112f, m*0x1p112f);
        sP[tid] = p;
    }
    if (tid == 0) {
        float s = 0.0f;
        #pragma unroll
        for (int i = 0; i < LAYERS; i++) s += gates[i];
        sG = s;
    }
    __syncthreads();

    // 8 rows per thread = 4 float4 = 4 independent chains (2x f32, 2x h2).
    const long long gt = (long long)blockIdx.x * TPB + tid;
    const long long f4 = gt * 4;
    if (f4 >= n4) return;
    const bool h1 = (f4 + 1) < n4, h2b = (f4 + 2) < n4, h3 = (f4 + 3) < n4;

    float4 A0 = x[f4];
    float4 A1 = h1  ? x[f4 + 1] : make_float4(0,0,0,0);
    float4 C0 = h2b ? x[f4 + 2] : make_float4(0,0,0,0);
    float4 C1 = h3  ? x[f4 + 3] : make_float4(0,0,0,0);

    u64 Xa0 = pk2(A0.x, A0.z), Ya0 = pk2(A0.y, A0.w);   // rows 0,1: f32 tanh
    u64 Xa1 = pk2(A1.x, A1.z), Ya1 = pk2(A1.y, A1.w);   // rows 2,3: f32 tanh
    u64 Xc0 = pk2(C0.x, C0.z), Yc0 = pk2(C0.y, C0.w);   // rows 4,5: h2 tanh
    u64 Xc1 = pk2(C1.x, C1.z), Yc1 = pk2(C1.y, C1.w);   // rows 6,7: h2 tanh

    #pragma unroll 4
    for (int l = 0; l < LAYERS; l++) {
        const LayerP p = sP[l];

        // args for all 4 groups (24 FFMA2 total incl. residuals below)
        u64 gA0x = fma2(p.w00, Xa0, fma2(p.w01, Ya0, p.b0));
        u64 gA0y = fma2(p.w10, Xa0, fma2(p.w11, Ya0, p.b1));
        u64 gA1x = fma2(p.w00, Xa1, fma2(p.w01, Ya1, p.b0));
        u64 gA1y = fma2(p.w10, Xa1, fma2(p.w11, Ya1, p.b1));
        u64 gC0x = fma2(p.w00, Xc0, fma2(p.w01, Yc0, p.b0));
        u64 gC0y = fma2(p.w10, Xc0, fma2(p.w11, Yc0, p.b1));
        u64 gC1x = fma2(p.w00, Xc1, fma2(p.w01, Yc1, p.b0));
        u64 gC1y = fma2(p.w10, Xc1, fma2(p.w11, Yc1, p.b1));

        float a0,a1,a2,a3,a4,a5,a6,a7;
        up2(a0, a1, gA0x); up2(a2, a3, gA0y);
        up2(a4, a5, gA1x); up2(a6, a7, gA1y);
        float c0,c1,c2,c3,c4,c5,c6,c7;
        up2(c0, c1, gC0x); up2(c2, c3, gC0y);
        up2(c4, c5, gC1x); up2(c6, c7, gC1y);

        // packs first (fixed pipe), then all 12 XU ops back-to-back
        unsigned hX0 = pack_h2(c1, c0);
        unsigned hY0 = pack_h2(c3, c2);
        unsigned hX1 = pack_h2(c5, c4);
        unsigned hY1 = pack_h2(c7, c6);

        float t0 = tanh_f32(a0), t1 = tanh_f32(a1);
        float t2 = tanh_f32(a2), t3 = tanh_f32(a3);
        float t4 = tanh_f32(a4), t5 = tanh_f32(a5);
        float t6 = tanh_f32(a6), t7 = tanh_f32(a7);
        hX0 = tanh_h2(hX0); hY0 = tanh_h2(hY0);
        hX1 = tanh_h2(hX1); hY1 = tanh_h2(hY1);

        Xa0 = fma2(p.m, pk2(t0, t1), Xa0);
        Ya0 = fma2(p.m, pk2(t2, t3), Ya0);
        Xa1 = fma2(p.m, pk2(t4, t5), Xa1);
        Ya1 = fma2(p.m, pk2(t6, t7), Ya1);

        // residual: state += (tanh16 * 2^-112) * (m * 2^112) -- single rounding
        Xc0 = fma2(p.m112, pk2(mag_lo(hX0), mag_hi(hX0)), Xc0);
        Yc0 = fma2(p.m112, pk2(mag_lo(hY0), mag_hi(hY0)), Yc0);
        Xc1 = fma2(p.m112, pk2(mag_lo(hX1), mag_hi(hX1)), Xc1);
        Yc1 = fma2(p.m112, pk2(mag_lo(hY1), mag_hi(hY1)), Yc1);
    }

    const float g = sG;
    const u64 g2 = pk2(g, g);
    Xa0 = mul2(g2, Xa0); Ya0 = mul2(g2, Ya0);
    Xa1 = mul2(g2, Xa1); Ya1 = mul2(g2, Ya1);
    Xc0 = mul2(g2, Xc0); Yc0 = mul2(g2, Yc0);
    Xc1 = mul2(g2, Xc1); Yc1 = mul2(g2, Yc1);

    float x0, x1, y0, y1;
    up2(x0, x1, Xa0); up2(y0, y1, Ya0);
    out[f4] = make_float4(x0, y0, x1, y1);
    if (h1)  { up2(x0, x1, Xa1); up2(y0, y1, Ya1); out[f4+1] = make_float4(x0, y0, x1, y1); }
    if (h2b) { up2(x0, x1, Xc0); up2(y0, y1, Yc0); out[f4+2] = make_float4(x0, y0, x1, y1); }
    if (h3)  { up2(x0, x1, Xc1); up2(y0, y1, Yc1); out[f4+3] = make_float4(x0, y0, x1, y1); }
}

extern "C" void kernel_launch(void* const* d_in, const int* in_sizes, int n_in,
                              void* d_out, int out_size)
{
    const float4* x     = (const float4*)d_in[0];
    const float*  W     = (const float*) d_in[1];
    const float*  b     = (const float*) d_in[2];
    const float*  masks = (const float*) d_in[3];
    const float*  gates = (const float*) d_in[4];
    float4* out = (float4*)d_out;

    const long long nfloat = (long long)in_sizes[0];   // BATCH * 2
    const long long n4 = nfloat / 4;                   // BATCH / 2
    const long long threads = (n4 + 3) / 4;            // 4 float4 per thread
    const int blocks = (int)((threads + TPB - 1) / TPB);
    rdb_kernel<<<blocks, TPB>>>(x, W, b, masks, gates, out, n4);
}

// round 16
// speedup vs baseline: 1.1074x; 1.1074x over previous
#include <cuda_runtime.h>

// ResidualDenseBlock: out = scan_{l=0..63}( tanh(out @ W[l]^T + b[l]) * m[l] + out ) * sum(gates)
//
// R16 = R4's exact instruction mix (FFMA2 + f32 tanh on half rows + f16x2 tanh
// with cvt pack/unpack on the other half) with ONLY the ILP doubled:
// 8 rows/thread = 4 independent dependency chains. Single-variable experiment:
// R4 (61 cyc/4rows) is latency-bound per pipe audit; more chains should close
// toward its XU floor (~48).

#define LAYERS 64
#define TPB    256

typedef unsigned long long u64;

__device__ __forceinline__ float tanh_f32(float x) {
    float y;
    asm("tanh.approx.f32 %0, %1;" : "=f"(y) : "f"(x));
    return y;
}
__device__ __forceinline__ unsigned tanh_h2(unsigned h) {
    unsigned r;
    asm("tanh.approx.f16x2 %0, %1;" : "=r"(r) : "r"(h));
    return r;
}
// d = { hi = cvt(%1), lo = cvt(%2) }
__device__ __forceinline__ unsigned pack_h2(float hi, float lo) {
    unsigned r;
    asm("cvt.rn.f16x2.f32 %0, %1, %2;" : "=r"(r) : "f"(hi), "f"(lo));
    return r;
}
__device__ __forceinline__ void unpack_h2(float& lo, float& hi, unsigned h) {
    asm("{.reg .b16 l, u;\n\t"
        " mov.b32 {l, u}, %2;\n\t"
        " cvt.f32.f16 %0, l;\n\t"
        " cvt.f32.f16 %1, u;}"
        : "=f"(lo), "=f"(hi) : "r"(h));
}
__device__ __forceinline__ u64 fma2(u64 a, u64 b, u64 c) {
    u64 d;
    asm("fma.rn.f32x2 %0, %1, %2, %3;" : "=l"(d) : "l"(a), "l"(b), "l"(c));
    return d;
}
__device__ __forceinline__ u64 mul2(u64 a, u64 b) {
    u64 d;
    asm("mul.rn.f32x2 %0, %1, %2;" : "=l"(d) : "l"(a), "l"(b));
    return d;
}
__device__ __forceinline__ u64 pk2(float lo, float hi) {
    u64 d;
    asm("mov.b64 %0, {%1, %2};" : "=l"(d) : "f"(lo), "f"(hi));
    return d;
}
__device__ __forceinline__ void up2(float& lo, float& hi, u64 s) {
    asm("mov.b64 {%0, %1}, %2;" : "=f"(lo), "=f"(hi) : "l"(s));
}

struct __align__(16) LayerP {
    u64 w00, w01, w10, w11, b0, b1, m, pad;   // broadcast (v,v) pairs
};

__global__ __launch_bounds__(TPB)
void rdb_kernel(const float4* __restrict__ x,
                const float*  __restrict__ W,
                const float*  __restrict__ b,
                const float*  __restrict__ masks,
                const float*  __restrict__ gates,
                float4* __restrict__ out,
                long long n4)
{
    __shared__ LayerP sP[LAYERS];
    __shared__ float  sG;

    const int tid = threadIdx.x;
    if (tid < LAYERS) {
        float w00 = W[tid*4+0], w01 = W[tid*4+1];
        float w10 = W[tid*4+2], w11 = W[tid*4+3];
        float b0 = b[tid*2+0], b1 = b[tid*2+1];
        float m = masks[tid];
        LayerP p;
        p.w00 = pk2(w00, w00); p.w01 = pk2(w01, w01);
        p.w10 = pk2(w10, w10); p.w11 = pk2(w11, w11);
        p.b0  = pk2(b0, b0);   p.b1  = pk2(b1, b1);
        p.m   = pk2(m, m);     p.pad = 0;
        sP[tid] = p;
    }
    if (tid == 0) {
        float s = 0.0f;
        #pragma unroll
        for (int i = 0; i < LAYERS; i++) s += gates[i];
        sG = s;
    }
    __syncthreads();

    const long long gt = (long long)blockIdx.x * TPB + tid;
    const long long f4 = gt * 4;
    if (f4 >= n4) return;
    const bool h1 = (f4 + 1) < n4, hc0 = (f4 + 2) < n4, hc1 = (f4 + 3) < n4;

    float4 A0 = x[f4];
    float4 A1 = h1  ? x[f4 + 1] : make_float4(0,0,0,0);
    float4 C0 = hc0 ? x[f4 + 2] : make_float4(0,0,0,0);
    float4 C1 = hc1 ? x[f4 + 3] : make_float4(0,0,0,0);

    u64 Xa0 = pk2(A0.x, A0.z), Ya0 = pk2(A0.y, A0.w);   // rows 0,1: f32 tanh
    u64 Xa1 = pk2(A1.x, A1.z), Ya1 = pk2(A1.y, A1.w);   // rows 2,3: f32 tanh
    u64 Xc0 = pk2(C0.x, C0.z), Yc0 = pk2(C0.y, C0.w);   // rows 4,5: h2 tanh
    u64 Xc1 = pk2(C1.x, C1.z), Yc1 = pk2(C1.y, C1.w);   // rows 6,7: h2 tanh

    #pragma unroll 4
    for (int l = 0; l < LAYERS; l++) {
        const LayerP p = sP[l];

        // ---- chains A0, A1 (f32 tanh), exactly R4's pattern x2 ----
        u64 gA0x = fma2(p.w00, Xa0, fma2(p.w01, Ya0, p.b0));
        u64 gA0y = fma2(p.w10, Xa0, fma2(p.w11, Ya0, p.b1));
        u64 gA1x = fma2(p.w00, Xa1, fma2(p.w01, Ya1, p.b0));
        u64 gA1y = fma2(p.w10, Xa1, fma2(p.w11, Ya1, p.b1));
        {
            float a0, a1, b0f, b1f, a4, a5, b4, b5;
            up2(a0, a1, gA0x);
            up2(b0f, b1f, gA0y);
            up2(a4, a5, gA1x);
            up2(b4, b5, gA1y);
            u64 tX0 = pk2(tanh_f32(a0), tanh_f32(a1));
            u64 tY0 = pk2(tanh_f32(b0f), tanh_f32(b1f));
            u64 tX1 = pk2(tanh_f32(a4), tanh_f32(a5));
            u64 tY1 = pk2(tanh_f32(b4), tanh_f32(b5));
            Xa0 = fma2(p.m, tX0, Xa0);
            Ya0 = fma2(p.m, tY0, Ya0);
            Xa1 = fma2(p.m, tX1, Xa1);
            Ya1 = fma2(p.m, tY1, Ya1);
        }

        // ---- chains C0, C1 (f16x2 tanh with cvt pack/unpack), R4's pattern x2 ----
        u64 gC0x = fma2(p.w00, Xc0, fma2(p.w01, Yc0, p.b0));
        u64 gC0y = fma2(p.w10, Xc0, fma2(p.w11, Yc0, p.b1));
        u64 gC1x = fma2(p.w00, Xc1, fma2(p.w01, Yc1, p.b0));
        u64 gC1y = fma2(p.w10, Xc1, fma2(p.w11, Yc1, p.b1));
        {
            float a0, a1, b0f, b1f, a4, a5, b4, b5;
            up2(a0, a1, gC0x);
            up2(b0f, b1f, gC0y);
            up2(a4, a5, gC1x);
            up2(b4, b5, gC1y);
            unsigned hX0 = tanh_h2(pack_h2(a1, a0));
            unsigned hY0 = tanh_h2(pack_h2(b1f, b0f));
            unsigned hX1 = tanh_h2(pack_h2(a5, a4));
            unsigned hY1 = tanh_h2(pack_h2(b5, b4));
            float t0, t1, t2, t3, t4, t5, t6, t7;
            unpack_h2(t0, t1, hX0);
            unpack_h2(t2, t3, hY0);
            unpack_h2(t4, t5, hX1);
            unpack_h2(t6, t7, hY1);
            Xc0 = fma2(p.m, pk2(t0, t1), Xc0);
            Yc0 = fma2(p.m, pk2(t2, t3), Yc0);
            Xc1 = fma2(p.m, pk2(t4, t5), Xc1);
            Yc1 = fma2(p.m, pk2(t6, t7), Yc1);
        }
    }

    const float g = sG;
    const u64 g2 = pk2(g, g);
    Xa0 = mul2(g2, Xa0); Ya0 = mul2(g2, Ya0);
    Xa1 = mul2(g2, Xa1); Ya1 = mul2(g2, Ya1);
    Xc0 = mul2(g2, Xc0); Yc0 = mul2(g2, Yc0);
    Xc1 = mul2(g2, Xc1); Yc1 = mul2(g2, Yc1);

    float x0, x1, y0, y1;
    up2(x0, x1, Xa0); up2(y0, y1, Ya0);
    out[f4] = make_float4(x0, y0, x1, y1);
    if (h1)  { up2(x0, x1, Xa1); up2(y0, y1, Ya1); out[f4+1] = make_float4(x0, y0, x1, y1); }
    if (hc0) { up2(x0, x1, Xc0); up2(y0, y1, Yc0); out[f4+2] = make_float4(x0, y0, x1, y1); }
    if (hc1) { up2(x0, x1, Xc1); up2(y0, y1, Yc1); out[f4+3] = make_float4(x0, y0, x1, y1); }
}

extern "C" void kernel_launch(void* const* d_in, const int* in_sizes, int n_in,
                              void* d_out, int out_size)
{
    const float4* x     = (const float4*)d_in[0];
    const float*  W     = (const float*) d_in[1];
    const float*  b     = (const float*) d_in[2];
    const float*  masks = (const float*) d_in[3];
    const float*  gates = (const float*) d_in[4];
    float4* out = (float4*)d_out;

    const long long nfloat = (long long)in_sizes[0];   // BATCH * 2
    const long long n4 = nfloat / 4;                   // BATCH / 2
    const long long threads = (n4 + 3) / 4;            // 4 float4 per thread
    const int blocks = (int)((threads + TPB - 1) / TPB);
    rdb_kernel<<<blocks, TPB>>>(x, W, b, masks, gates, out, n4);
}

// round 17
// speedup vs baseline: 1.1800x; 1.0656x over previous
#include <cuda_runtime.h>

// ResidualDenseBlock: out = scan_{l=0..63}( tanh(out @ W[l]^T + b[l]) * m[l] + out ) * sum(gates)
//
// R17: partial MUFU offload. R16 proved the kernel is XU(MUFU)-throughput-bound
// at 64 cyc/layer/warp (f16x2 tanh is half-rate; ILP-doubling changed nothing).
// Offload 25% of tanhs (rows 6,7 of 8/thread) to a 4-byte tangent LUT in smem:
// entry i = tanh(midpoint of log-segment i); eval = tval + (1-tval^2)*(|v|-xmid),
// sign by OR. Costs 1 LDS.32 + 3 FMA + ~4 ALU, zero MUFU. MUFU drops to
// 0.75*roofline = 170K cyc (binder); smem ~96K, issue ~110K stay under.

#define LAYERS 64
#define TPB    256
#define TAB_N  4096    // 8 exp bits + 4 mantissa bits, 4B each = 16KB

typedef unsigned long long u64;

__device__ __forceinline__ float tanh_f32(float x) {
    float y;
    asm("tanh.approx.f32 %0, %1;" : "=f"(y) : "f"(x));
    return y;
}
__device__ __forceinline__ u64 fma2(u64 a, u64 b, u64 c) {
    u64 d;
    asm("fma.rn.f32x2 %0, %1, %2, %3;" : "=l"(d) : "l"(a), "l"(b), "l"(c));
    return d;
}
__device__ __forceinline__ u64 mul2(u64 a, u64 b) {
    u64 d;
    asm("mul.rn.f32x2 %0, %1, %2;" : "=l"(d) : "l"(a), "l"(b));
    return d;
}
__device__ __forceinline__ u64 pk2(float lo, float hi) {
    u64 d;
    asm("mov.b64 %0, {%1, %2};" : "=l"(d) : "f"(lo), "f"(hi));
    return d;
}
__device__ __forceinline__ void up2(float& lo, float& hi, u64 s) {
    asm("mov.b64 {%0, %1}, %2;" : "=f"(lo), "=f"(hi) : "l"(s));
}

// Tangent-line tanh from a 4-byte/entry log-indexed table. Zero MUFU ops.
// entry covers [2^e(1+m/16), 2^e(1+(m+1)/16)); stores tanh(bit-midpoint).
__device__ __forceinline__ float lut_tanh(float v, const float* tab) {
    unsigned bi = __float_as_uint(v);
    unsigned addr = (bi >> 17) & 0x3FFCu;                 // entry*4, sign dropped
    float tval;
    asm("ld.shared.f32 %0, [%1];" : "=f"(tval)
        : "r"((unsigned)__cvta_generic_to_shared(tab) + addr));
    float xm = __uint_as_float((bi & 0x7FF80000u) | 0x00040000u);  // segment midpoint
    float d  = fmaf(-tval, tval, 1.0f);                   // tanh' = 1 - t^2
    float t  = fmaf(d, fabsf(v) - xm, tval);              // tangent line (t >= 0)
    return __uint_as_float(__float_as_uint(t) | (bi & 0x80000000u)); // odd symmetry
}

struct __align__(16) LayerP {
    u64 w00, w01, w10, w11, b0, b1, m, pad;   // broadcast (v,v) pairs
};

__global__ __launch_bounds__(TPB)
void rdb_kernel(const float4* __restrict__ x,
                const float*  __restrict__ W,
                const float*  __restrict__ b,
                const float*  __restrict__ masks,
                const float*  __restrict__ gates,
                float4* __restrict__ out,
                long long n4)
{
    __shared__ float  tab[TAB_N];    // 16 KB
    __shared__ LayerP sP[LAYERS];    // 4 KB
    __shared__ float  sG;

    const int tid = threadIdx.x;

    // build tangent table: midpoint of log-segment i has bits (i<<19)|0x40000
    for (int i = tid; i < TAB_N; i += TPB) {
        float xm = __uint_as_float(((unsigned)i << 19) | 0x00040000u);
        tab[i] = tanh_f32(xm);
    }

    if (tid < LAYERS) {
        float w00 = W[tid*4+0], w01 = W[tid*4+1];
        float w10 = W[tid*4+2], w11 = W[tid*4+3];
        float b0 = b[tid*2+0], b1 = b[tid*2+1];
        float m = masks[tid];
        LayerP p;
        p.w00 = pk2(w00, w00); p.w01 = pk2(w01, w01);
        p.w10 = pk2(w10, w10); p.w11 = pk2(w11, w11);
        p.b0  = pk2(b0, b0);   p.b1  = pk2(b1, b1);
        p.m   = pk2(m, m);     p.pad = 0;
        sP[tid] = p;
    }
    if (tid == 0) {
        float s = 0.0f;
        #pragma unroll
        for (int i = 0; i < LAYERS; i++) s += gates[i];
        sG = s;
    }
    __syncthreads();

    // 8 rows/thread: pairs A0,A1,A2 (rows 0-5) on MUFU; pair C (rows 6,7) on LUT.
    const long long gt = (long long)blockIdx.x * TPB + tid;
    const long long f4 = gt * 4;
    if (f4 >= n4) return;
    const bool h1 = (f4 + 1) < n4, h2b = (f4 + 2) < n4, h3 = (f4 + 3) < n4;

    float4 A0 = x[f4];
    float4 A1 = h1  ? x[f4 + 1] : make_float4(0,0,0,0);
    float4 A2 = h2b ? x[f4 + 2] : make_float4(0,0,0,0);
    float4 C0 = h3  ? x[f4 + 3] : make_float4(0,0,0,0);

    u64 Xa0 = pk2(A0.x, A0.z), Ya0 = pk2(A0.y, A0.w);
    u64 Xa1 = pk2(A1.x, A1.z), Ya1 = pk2(A1.y, A1.w);
    u64 Xa2 = pk2(A2.x, A2.z), Ya2 = pk2(A2.y, A2.w);
    u64 Xc  = pk2(C0.x, C0.z), Yc  = pk2(C0.y, C0.w);

    #pragma unroll 4
    for (int l = 0; l < LAYERS; l++) {
        const LayerP p = sP[l];

        u64 g0x = fma2(p.w00, Xa0, fma2(p.w01, Ya0, p.b0));
        u64 g0y = fma2(p.w10, Xa0, fma2(p.w11, Ya0, p.b1));
        u64 g1x = fma2(p.w00, Xa1, fma2(p.w01, Ya1, p.b0));
        u64 g1y = fma2(p.w10, Xa1, fma2(p.w11, Ya1, p.b1));
        u64 g2x = fma2(p.w00, Xa2, fma2(p.w01, Ya2, p.b0));
        u64 g2y = fma2(p.w10, Xa2, fma2(p.w11, Ya2, p.b1));
        u64 gcx = fma2(p.w00, Xc,  fma2(p.w01, Yc,  p.b0));
        u64 gcy = fma2(p.w10, Xc,  fma2(p.w11, Yc,  p.b1));

        float a0,a1,a2,a3,a4,a5,a6,a7,a8,a9,aA,aB;
        up2(a0, a1, g0x); up2(a2, a3, g0y);
        up2(a4, a5, g1x); up2(a6, a7, g1y);
        up2(a8, a9, g2x); up2(aA, aB, g2y);
        float c0, c1, c2, c3;
        up2(c0, c1, gcx); up2(c2, c3, gcy);

        // 12 MUFU tanh (rows 0-5), issued back-to-back
        float t0 = tanh_f32(a0), t1 = tanh_f32(a1);
        float t2 = tanh_f32(a2), t3 = tanh_f32(a3);
        float t4 = tanh_f32(a4), t5 = tanh_f32(a5);
        float t6 = tanh_f32(a6), t7 = tanh_f32(a7);
        float t8 = tanh_f32(a8), t9 = tanh_f32(a9);
        float tA = tanh_f32(aA), tB = tanh_f32(aB);

        // 4 LUT tanh (rows 6,7): LDS + FMA + ALU only
        float u0 = lut_tanh(c0, tab);
        float u1 = lut_tanh(c1, tab);
        float u2 = lut_tanh(c2, tab);
        float u3 = lut_tanh(c3, tab);

        Xa0 = fma2(p.m, pk2(t0, t1), Xa0);
        Ya0 = fma2(p.m, pk2(t2, t3), Ya0);
        Xa1 = fma2(p.m, pk2(t4, t5), Xa1);
        Ya1 = fma2(p.m, pk2(t6, t7), Ya1);
        Xa2 = fma2(p.m, pk2(t8, t9), Xa2);
        Ya2 = fma2(p.m, pk2(tA, tB), Ya2);
        Xc  = fma2(p.m, pk2(u0, u1), Xc);
        Yc  = fma2(p.m, pk2(u2, u3), Yc);
    }

    const float g = sG;
    const u64 g2 = pk2(g, g);
    Xa0 = mul2(g2, Xa0); Ya0 = mul2(g2, Ya0);
    Xa1 = mul2(g2, Xa1); Ya1 = mul2(g2, Ya1);
    Xa2 = mul2(g2, Xa2); Ya2 = mul2(g2, Ya2);
    Xc  = mul2(g2, Xc);  Yc  = mul2(g2, Yc);

    float x0, x1, y0, y1;
    up2(x0, x1, Xa0); up2(y0, y1, Ya0);
    out[f4] = make_float4(x0, y0, x1, y1);
    if (h1)  { up2(x0, x1, Xa1); up2(y0, y1, Ya1); out[f4+1] = make_float4(x0, y0, x1, y1); }
    if (h2b) { up2(x0, x1, Xa2); up2(y0, y1, Ya2); out[f4+2] = make_float4(x0, y0, x1, y1); }
    if (h3)  { up2(x0, x1, Xc);  up2(y0, y1, Yc);  out[f4+3] = make_float4(x0, y0, x1, y1); }
}

extern "C" void kernel_launch(void* const* d_in, const int* in_sizes, int n_in,
                              void* d_out, int out_size)
{
    const float4* x     = (const float4*)d_in[0];
    const float*  W     = (const float*) d_in[1];
    const float*  b     = (const float*) d_in[2];
    const float*  masks = (const float*) d_in[3];
    const float*  gates = (const float*) d_in[4];
    float4* out = (float4*)d_out;

    const long long nfloat = (long long)in_sizes[0];   // BATCH * 2
    const long long n4 = nfloat / 4;                   // BATCH / 2
    const long long threads = (n4 + 3) / 4;            // 4 float4 per thread
    const int blocks = (int)((threads + TPB - 1) / TPB);
    rdb_kernel<<<blocks, TPB>>>(x, W, b, masks, gates, out, n4);
}